// round 1
// baseline (speedup 1.0000x reference)
#include <cuda_runtime.h>

// RetNet retention fused kernel:
//   scores = Q @ K^T           [B,H,S,S]
//   MSR    = scores * D        (per-head decay mask, broadcast over batch)
//   out    = MSR @ V           [B,H,S,DH]
// Outputs concatenated into d_out: [out (B*H*S*DH) | MSR (B*H*S*S)] fp32.
//
// Strategy: flash-style fused loop per (b,h,q-tile). 64x64 tiles, 256 threads,
// 4x4 register tiles, packed fma.rn.f32x2 (Blackwell f32x2) to halve FMA-pipe
// instruction count. Full fp32 accuracy.

#define S_LEN 2048
#define DHEAD 64
#define H_NUM 16
#define BM 64
#define BN 64

typedef unsigned long long u64;

__device__ __forceinline__ u64 pack2(float lo, float hi) {
    u64 r;
    asm("mov.b64 %0, {%1, %2};" : "=l"(r) : "f"(lo), "f"(hi));
    return r;
}
__device__ __forceinline__ u64 fma2(u64 a, u64 b, u64 c) {
    u64 d;
    asm("fma.rn.f32x2 %0, %1, %2, %3;" : "=l"(d) : "l"(a), "l"(b), "l"(c));
    return d;
}
__device__ __forceinline__ float2 unpack2(u64 v) {
    float2 f;
    asm("mov.b64 {%0, %1}, %2;" : "=f"(f.x), "=f"(f.y) : "l"(v));
    return f;
}

__global__ __launch_bounds__(256) void retnet_msr_kernel(
    const float* __restrict__ Q, const float* __restrict__ K,
    const float* __restrict__ V, const float* __restrict__ Dm,
    float* __restrict__ Out, float* __restrict__ Msr)
{
    // Qs: [d][i] transposed (pitch BM)   — vectorized i-reads in gemm1
    // Ks: [d][j] transposed (pitch BN)   — vectorized j-reads in gemm1,
    //     reused as Ms[i][j] natural     — rows for gemm2
    // Vs: [j][d] natural (pitch DHEAD)   — vectorized d-reads in gemm2
    __shared__ float Qs[DHEAD * BM];
    __shared__ float Ks[DHEAD * BN];
    __shared__ float Vs[BN * DHEAD];

    const int qt  = blockIdx.x;          // q tile: 0..S/BM-1
    const int bh  = blockIdx.y;          // 0..B*H-1
    const int h   = bh & (H_NUM - 1);
    const int tid = threadIdx.x;
    const int tx  = tid & 15;            // 0..15 -> 4 cols each
    const int ty  = tid >> 4;            // 0..15 -> 4 rows each
    const int q0  = qt * BM;

    const size_t bh_qkv = (size_t)bh * S_LEN * DHEAD;
    const float* Qg = Q  + bh_qkv + (size_t)q0 * DHEAD;
    const float* Kg = K  + bh_qkv;
    const float* Vg = V  + bh_qkv;
    const float* Dg = Dm + (size_t)h  * S_LEN * S_LEN + (size_t)q0 * S_LEN;
    float*       Og = Out + bh_qkv + (size_t)q0 * DHEAD;
    float*       Mg = Msr + (size_t)bh * S_LEN * S_LEN + (size_t)q0 * S_LEN;

    // ---- load Q tile transposed: Qs[d][i] -------------------------------
    {
        const int i  = tid & 63;     // 32 distinct rows per warp -> bank-conflict-free STS
        const int cg = tid >> 6;     // 0..3
        #pragma unroll
        for (int c = 0; c < 4; ++c) {
            const int f4 = cg * 4 + c;
            float4 v = *(const float4*)(Qg + (size_t)i * DHEAD + f4 * 4);
            Qs[(f4 * 4 + 0) * BM + i] = v.x;
            Qs[(f4 * 4 + 1) * BM + i] = v.y;
            Qs[(f4 * 4 + 2) * BM + i] = v.z;
            Qs[(f4 * 4 + 3) * BM + i] = v.w;
        }
    }

    u64 acc_o[4][2];
    #pragma unroll
    for (int r = 0; r < 4; ++r) { acc_o[r][0] = 0ull; acc_o[r][1] = 0ull; }

    for (int kt = 0; kt < S_LEN / BN; ++kt) {
        const int k0 = kt * BN;

        __syncthreads();  // everyone done with Ks(as Ms)/Vs from prev iter

        // ---- load K tile transposed: Ks[d][j] ---------------------------
        {
            const int j  = tid & 63;
            const int cg = tid >> 6;
            #pragma unroll
            for (int c = 0; c < 4; ++c) {
                const int f4 = cg * 4 + c;
                float4 v = *(const float4*)(Kg + (size_t)(k0 + j) * DHEAD + f4 * 4);
                Ks[(f4 * 4 + 0) * BN + j] = v.x;
                Ks[(f4 * 4 + 1) * BN + j] = v.y;
                Ks[(f4 * 4 + 2) * BN + j] = v.z;
                Ks[(f4 * 4 + 3) * BN + j] = v.w;
            }
        }
        // ---- load V tile natural: Vs[j][d] (fully coalesced) ------------
        #pragma unroll
        for (int t = 0; t < 4; ++t) {
            const int f4 = tid + t * 256;        // 0..1023
            const int j  = f4 >> 4;
            const int d0 = (f4 & 15) * 4;
            *(float4*)(Vs + j * DHEAD + d0) =
                *(const float4*)(Vg + (size_t)(k0 + j) * DHEAD + d0);
        }
        __syncthreads();

        // ---- gemm1: S[i][j] = sum_d Q[i][d] * K[j][d] -------------------
        u64 acc_s[4][2];
        #pragma unroll
        for (int r = 0; r < 4; ++r) { acc_s[r][0] = 0ull; acc_s[r][1] = 0ull; }

        #pragma unroll 8
        for (int d = 0; d < DHEAD; ++d) {
            float4 a = *(const float4*)(Qs + d * BM + ty * 4);
            float4 b = *(const float4*)(Ks + d * BN + tx * 4);
            u64 b01 = pack2(b.x, b.y);
            u64 b23 = pack2(b.z, b.w);
            u64 a0 = pack2(a.x, a.x);
            u64 a1 = pack2(a.y, a.y);
            u64 a2 = pack2(a.z, a.z);
            u64 a3 = pack2(a.w, a.w);
            acc_s[0][0] = fma2(a0, b01, acc_s[0][0]);
            acc_s[0][1] = fma2(a0, b23, acc_s[0][1]);
            acc_s[1][0] = fma2(a1, b01, acc_s[1][0]);
            acc_s[1][1] = fma2(a1, b23, acc_s[1][1]);
            acc_s[2][0] = fma2(a2, b01, acc_s[2][0]);
            acc_s[2][1] = fma2(a2, b23, acc_s[2][1]);
            acc_s[3][0] = fma2(a3, b01, acc_s[3][0]);
            acc_s[3][1] = fma2(a3, b23, acc_s[3][1]);
        }
        __syncthreads();  // done reading Ks -> safe to overwrite as Ms

        // ---- decay mask, MSR global store, Ms smem store ----------------
        #pragma unroll
        for (int r = 0; r < 4; ++r) {
            const int i = ty * 4 + r;
            float2 s01 = unpack2(acc_s[r][0]);
            float2 s23 = unpack2(acc_s[r][1]);
            float4 dv = *(const float4*)(Dg + (size_t)i * S_LEN + k0 + tx * 4);
            float4 m;
            m.x = s01.x * dv.x;
            m.y = s01.y * dv.y;
            m.z = s23.x * dv.z;
            m.w = s23.y * dv.w;
            *(float4*)(Mg + (size_t)i * S_LEN + k0 + tx * 4) = m;
            *(float4*)(Ks + i * BN + tx * 4) = m;   // Ms[i][j], natural
        }
        __syncthreads();  // Ms ready

        // ---- gemm2: Out[i][d] += sum_j Ms[i][j] * V[j][d] ---------------
        #pragma unroll 4
        for (int j4 = 0; j4 < BN / 4; ++j4) {
            float4 m0 = *(const float4*)(Ks + (ty * 4 + 0) * BN + j4 * 4);
            float4 m1 = *(const float4*)(Ks + (ty * 4 + 1) * BN + j4 * 4);
            float4 m2 = *(const float4*)(Ks + (ty * 4 + 2) * BN + j4 * 4);
            float4 m3 = *(const float4*)(Ks + (ty * 4 + 3) * BN + j4 * 4);
            const float am0[4] = {m0.x, m0.y, m0.z, m0.w};
            const float am1[4] = {m1.x, m1.y, m1.z, m1.w};
            const float am2[4] = {m2.x, m2.y, m2.z, m2.w};
            const float am3[4] = {m3.x, m3.y, m3.z, m3.w};
            #pragma unroll
            for (int u = 0; u < 4; ++u) {
                const int j = j4 * 4 + u;
                float4 b = *(const float4*)(Vs + j * DHEAD + tx * 4);
                u64 b01 = pack2(b.x, b.y);
                u64 b23 = pack2(b.z, b.w);
                u64 a0 = pack2(am0[u], am0[u]);
                u64 a1 = pack2(am1[u], am1[u]);
                u64 a2 = pack2(am2[u], am2[u]);
                u64 a3 = pack2(am3[u], am3[u]);
                acc_o[0][0] = fma2(a0, b01, acc_o[0][0]);
                acc_o[0][1] = fma2(a0, b23, acc_o[0][1]);
                acc_o[1][0] = fma2(a1, b01, acc_o[1][0]);
                acc_o[1][1] = fma2(a1, b23, acc_o[1][1]);
                acc_o[2][0] = fma2(a2, b01, acc_o[2][0]);
                acc_o[2][1] = fma2(a2, b23, acc_o[2][1]);
                acc_o[3][0] = fma2(a3, b01, acc_o[3][0]);
                acc_o[3][1] = fma2(a3, b23, acc_o[3][1]);
            }
        }
    }

    // ---- write Out ------------------------------------------------------
    #pragma unroll
    for (int r = 0; r < 4; ++r) {
        const int i = ty * 4 + r;
        float2 o01 = unpack2(acc_o[r][0]);
        float2 o23 = unpack2(acc_o[r][1]);
        float4 o = make_float4(o01.x, o01.y, o23.x, o23.y);
        *(float4*)(Og + (size_t)i * DHEAD + tx * 4) = o;
    }
}

extern "C" void kernel_launch(void* const* d_in, const int* in_sizes, int n_in,
                              void* d_out, int out_size) {
    const float* Q  = (const float*)d_in[0];
    const float* K  = (const float*)d_in[1];
    const float* V  = (const float*)d_in[2];
    const float* Dm = (const float*)d_in[3];

    // B derived from Q size: B*H*S*DH elements
    const int B = in_sizes[0] / (H_NUM * S_LEN * DHEAD);

    float* Out = (float*)d_out;
    float* Msr = Out + (size_t)B * H_NUM * S_LEN * DHEAD;  // tuple order: (out, MSR)

    dim3 grid(S_LEN / BM, B * H_NUM);
    retnet_msr_kernel<<<grid, 256>>>(Q, K, V, Dm, Out, Msr);
}

// round 2
// speedup vs baseline: 1.0706x; 1.0706x over previous
#include <cuda_runtime.h>

// RetNet retention fused kernel, round 2:
//   scores = Q @ K^T ; MSR = scores * D ; out = MSR @ V
//   d_out = [out | MSR] fp32.
//
// 128x128 block tile, 256 threads, 8x8 (gemm1) / 8x4 (gemm2) register tiles,
// quadrant-split indexing for conflict-free/broadcast LDS, packed fma.rn.f32x2.
// Ms (masked scores) processed in two 64-col halves aliasing the K smem tile.

#define S_LEN 2048
#define DHEAD 64
#define H_NUM 16
#define BM 128
#define BN 128

typedef unsigned long long u64;

__device__ __forceinline__ u64 pack2(float lo, float hi) {
    u64 r;
    asm("mov.b64 %0, {%1, %2};" : "=l"(r) : "f"(lo), "f"(hi));
    return r;
}
__device__ __forceinline__ u64 fma2(u64 a, u64 b, u64 c) {
    u64 d;
    asm("fma.rn.f32x2 %0, %1, %2, %3;" : "=l"(d) : "l"(a), "l"(b), "l"(c));
    return d;
}
__device__ __forceinline__ u64 mul2(u64 a, u64 b) {
    u64 d;
    asm("mul.rn.f32x2 %0, %1, %2;" : "=l"(d) : "l"(a), "l"(b));
    return d;
}
__device__ __forceinline__ float2 unpack2(u64 v) {
    float2 f;
    asm("mov.b64 {%0, %1}, %2;" : "=f"(f.x), "=f"(f.y) : "l"(v));
    return f;
}

__global__ __launch_bounds__(256, 1) void retnet_msr_kernel(
    const float* __restrict__ Q, const float* __restrict__ K,
    const float* __restrict__ V, const float* __restrict__ Dm,
    float* __restrict__ Out, float* __restrict__ Msr)
{
    __shared__ float Qs[DHEAD * BM];   // [d][i], pitch 128
    __shared__ float Ks[DHEAD * BN];   // [d][j], pitch 128; aliased as Ms[i][jh], pitch 64
    __shared__ float Vs[BN * DHEAD];   // [j][d], pitch 64
    float* Ms = Ks;                    // 128 x 64 half-tile of masked scores

    const int qt  = blockIdx.x;
    const int bh  = blockIdx.y;
    const int h   = bh & (H_NUM - 1);
    const int tid = threadIdx.x;
    const int tx  = tid & 15;          // 16 col-groups
    const int ty  = tid >> 4;          // 16 row-groups
    const int q0  = qt * BM;

    const size_t bh_qkv = (size_t)bh * S_LEN * DHEAD;
    const float* Qg = Q  + bh_qkv + (size_t)q0 * DHEAD;
    const float* Kg = K  + bh_qkv;
    const float* Vg = V  + bh_qkv;
    const float* Dg = Dm + (size_t)h  * S_LEN * S_LEN + (size_t)q0 * S_LEN;
    float*       Og = Out + bh_qkv + (size_t)q0 * DHEAD;
    float*       Mg = Msr + (size_t)bh * S_LEN * S_LEN + (size_t)q0 * S_LEN;

    // ---- load Q tile transposed: Qs[d][i] (persistent for whole block) ----
    {
        const int i  = tid & 127;
        const int d0 = (tid >> 7) * 32;
        const float* src = Qg + (size_t)i * DHEAD + d0;
        #pragma unroll
        for (int c = 0; c < 8; ++c) {
            float4 v = *(const float4*)(src + c * 4);
            const int d = d0 + c * 4;
            Qs[(d + 0) * BM + i] = v.x;
            Qs[(d + 1) * BM + i] = v.y;
            Qs[(d + 2) * BM + i] = v.z;
            Qs[(d + 3) * BM + i] = v.w;
        }
    }

    // out accumulators: [iq][r] x 4 d-cols (2 pairs)
    u64 acc_o[2][4][2];
    #pragma unroll
    for (int iq = 0; iq < 2; ++iq)
        #pragma unroll
        for (int r = 0; r < 4; ++r) { acc_o[iq][r][0] = 0ull; acc_o[iq][r][1] = 0ull; }

    __syncthreads();

    for (int kt = 0; kt < S_LEN / BN; ++kt) {
        const int k0 = kt * BN;

        // ---- load K tile transposed: Ks[d][j] ----------------------------
        {
            const int j  = tid & 127;
            const int d0 = (tid >> 7) * 32;
            const float* src = Kg + (size_t)(k0 + j) * DHEAD + d0;
            #pragma unroll
            for (int c = 0; c < 8; ++c) {
                float4 v = *(const float4*)(src + c * 4);
                const int d = d0 + c * 4;
                Ks[(d + 0) * BN + j] = v.x;
                Ks[(d + 1) * BN + j] = v.y;
                Ks[(d + 2) * BN + j] = v.z;
                Ks[(d + 3) * BN + j] = v.w;
            }
        }
        // ---- load V tile natural: Vs[j][d], straight coalesced copy ------
        {
            const float4* src = (const float4*)(Vg + (size_t)k0 * DHEAD);
            float4*       dst = (float4*)Vs;
            #pragma unroll
            for (int t = 0; t < 8; ++t)
                dst[tid + t * 256] = src[tid + t * 256];
        }
        __syncthreads();

        // ---- gemm1: S[i][j] = sum_d Q[i][d] * K[j][d], 8x8 per thread ----
        u64 acc_s[2][2][4][2];   // [iq][jq][r][jpair]
        #pragma unroll
        for (int iq = 0; iq < 2; ++iq)
            #pragma unroll
            for (int jq = 0; jq < 2; ++jq)
                #pragma unroll
                for (int r = 0; r < 4; ++r) {
                    acc_s[iq][jq][r][0] = 0ull;
                    acc_s[iq][jq][r][1] = 0ull;
                }

        #pragma unroll 4
        for (int d = 0; d < DHEAD; ++d) {
            float4 aA = *(const float4*)(Qs + d * BM + ty * 4);
            float4 aB = *(const float4*)(Qs + d * BM + 64 + ty * 4);
            float4 bA = *(const float4*)(Ks + d * BN + tx * 4);
            float4 bB = *(const float4*)(Ks + d * BN + 64 + tx * 4);
            u64 b[2][2];
            b[0][0] = pack2(bA.x, bA.y); b[0][1] = pack2(bA.z, bA.w);
            b[1][0] = pack2(bB.x, bB.y); b[1][1] = pack2(bB.z, bB.w);
            const float aAv[4] = {aA.x, aA.y, aA.z, aA.w};
            const float aBv[4] = {aB.x, aB.y, aB.z, aB.w};
            #pragma unroll
            for (int r = 0; r < 4; ++r) {
                u64 a0 = pack2(aAv[r], aAv[r]);
                u64 a1 = pack2(aBv[r], aBv[r]);
                acc_s[0][0][r][0] = fma2(a0, b[0][0], acc_s[0][0][r][0]);
                acc_s[0][0][r][1] = fma2(a0, b[0][1], acc_s[0][0][r][1]);
                acc_s[0][1][r][0] = fma2(a0, b[1][0], acc_s[0][1][r][0]);
                acc_s[0][1][r][1] = fma2(a0, b[1][1], acc_s[0][1][r][1]);
                acc_s[1][0][r][0] = fma2(a1, b[0][0], acc_s[1][0][r][0]);
                acc_s[1][0][r][1] = fma2(a1, b[0][1], acc_s[1][0][r][1]);
                acc_s[1][1][r][0] = fma2(a1, b[1][0], acc_s[1][1][r][0]);
                acc_s[1][1][r][1] = fma2(a1, b[1][1], acc_s[1][1][r][1]);
            }
        }
        __syncthreads();   // done reading Ks -> safe to overwrite as Ms

        // ---- two 64-col halves: mask + MSR store, then gemm2 -------------
        #pragma unroll
        for (int half = 0; half < 2; ++half) {
            const int jg = k0 + half * 64 + tx * 4;   // global j of this thread's cols
            #pragma unroll
            for (int iq = 0; iq < 2; ++iq)
                #pragma unroll
                for (int r = 0; r < 4; ++r) {
                    const int i = iq * 64 + ty * 4 + r;
                    float4 dv = *(const float4*)(Dg + (size_t)i * S_LEN + jg);
                    u64 m01 = mul2(acc_s[iq][half][r][0], pack2(dv.x, dv.y));
                    u64 m23 = mul2(acc_s[iq][half][r][1], pack2(dv.z, dv.w));
                    float2 lo = unpack2(m01), hi = unpack2(m23);
                    float4 m = make_float4(lo.x, lo.y, hi.x, hi.y);
                    *(float4*)(Mg + (size_t)i * S_LEN + jg) = m;
                    *(float4*)(Ms + i * 64 + tx * 4)        = m;
                }
            __syncthreads();   // Ms half ready

            // gemm2: acc_o[i][d] += sum_jj Ms[i][jj] * V[half*64+jj][d]
            #pragma unroll 4
            for (int j4 = 0; j4 < 16; ++j4) {
                float4 mv[2][4];
                #pragma unroll
                for (int iq = 0; iq < 2; ++iq)
                    #pragma unroll
                    for (int r = 0; r < 4; ++r)
                        mv[iq][r] = *(const float4*)(Ms + (iq * 64 + ty * 4 + r) * 64 + j4 * 4);
                #pragma unroll
                for (int u = 0; u < 4; ++u) {
                    float4 bv = *(const float4*)(Vs + (half * 64 + j4 * 4 + u) * DHEAD + tx * 4);
                    u64 b01 = pack2(bv.x, bv.y);
                    u64 b23 = pack2(bv.z, bv.w);
                    #pragma unroll
                    for (int iq = 0; iq < 2; ++iq)
                        #pragma unroll
                        for (int r = 0; r < 4; ++r) {
                            const float mvv[4] = {mv[iq][r].x, mv[iq][r].y,
                                                  mv[iq][r].z, mv[iq][r].w};
                            u64 aa = pack2(mvv[u], mvv[u]);
                            acc_o[iq][r][0] = fma2(aa, b01, acc_o[iq][r][0]);
                            acc_o[iq][r][1] = fma2(aa, b23, acc_o[iq][r][1]);
                        }
                }
            }
            __syncthreads();   // done reading Ms half (and Vs on half==1)
        }
    }

    // ---- write Out: 8 rows x 4 d-cols per thread -------------------------
    #pragma unroll
    for (int iq = 0; iq < 2; ++iq)
        #pragma unroll
        for (int r = 0; r < 4; ++r) {
            const int i = iq * 64 + ty * 4 + r;
            float2 lo = unpack2(acc_o[iq][r][0]);
            float2 hi = unpack2(acc_o[iq][r][1]);
            *(float4*)(Og + (size_t)i * DHEAD + tx * 4) =
                make_float4(lo.x, lo.y, hi.x, hi.y);
        }
}

extern "C" void kernel_launch(void* const* d_in, const int* in_sizes, int n_in,
                              void* d_out, int out_size) {
    const float* Q  = (const float*)d_in[0];
    const float* K  = (const float*)d_in[1];
    const float* V  = (const float*)d_in[2];
    const float* Dm = (const float*)d_in[3];

    const int B = in_sizes[0] / (H_NUM * S_LEN * DHEAD);

    float* Out = (float*)d_out;
    float* Msr = Out + (size_t)B * H_NUM * S_LEN * DHEAD;   // tuple order: (out, MSR)

    dim3 grid(S_LEN / BM, B * H_NUM);
    retnet_msr_kernel<<<grid, 256>>>(Q, K, V, Dm, Out, Msr);
}